// round 16
// baseline (speedup 1.0000x reference)
#include <cuda_runtime.h>
#include <cuda_fp16.h>
#include <cstdint>
#include <math.h>

// Problem constants
#define BB   16      // batch
#define CI   2048    // input capsules
#define NI   16      // input capsule dim
#define CJ   64      // output capsules
#define NJ   32      // output capsule dim
#define JM   2048    // CJ*NJ
#define K1_CHUNK 2   // i's per prefix chunk (acc reset period)
#define K1_IBLK  4   // i's per K1 block
#define RT_ICHUNK 8                       // i's per window (== warps/block)
#define RT_WND    4                       // windows per block
#define RT_CH     (RT_ICHUNK / 2)         // 4 chunks per window
#define RT_BUFB   (RT_CH * 2 * 4096)      // 32KB per slab buffer
#define RT_SMEM   (2 * RT_BUFB + RT_ICHUNK * CJ * 4)   // 2 slabs + 2KB dsm
#define AL2E 11.541560327111707f          // 8 * log2(e)

typedef unsigned long long ull;
typedef unsigned int       uint;

// g_Uh: chunk-local PREFIX sums of u over i (chunk=2), fp16, layout [i][b][jm]
static __device__ __half g_Uh[(size_t)CI * BB * JM];  // 134 MB
static __device__ float  g_s[BB * JM];                // s accumulator (BSS zero)
static __device__ float  g_v[BB * JM];                // v0, then v0+v1

// ---- packed fp32 pair helpers (fma.rn.f32x2, sm_100+) ----------------------
__device__ __forceinline__ void fma2(ull& d, ull a, ull b) {
    asm("fma.rn.f32x2 %0, %1, %2, %0;" : "+l"(d) : "l"(a), "l"(b));
}
__device__ __forceinline__ ull pack2(float x, float y) {
    ull r; asm("mov.b64 %0, {%1, %2};" : "=l"(r) : "f"(x), "f"(y)); return r;
}
__device__ __forceinline__ float2 unpack2(ull v) {
    float2 r; asm("mov.b64 {%0, %1}, %2;" : "=f"(r.x), "=f"(r.y) : "l"(v)); return r;
}

// ---- cp.async helpers -------------------------------------------------------
__device__ __forceinline__ void cp16(uint s, const void* g) {
    asm volatile("cp.async.cg.shared.global [%0], [%1], 16;"
                 :: "r"(s), "l"(g) : "memory");
}
__device__ __forceinline__ void cp_commit() {
    asm volatile("cp.async.commit_group;" ::: "memory");
}
template<int N> __device__ __forceinline__ void cp_waitN() {
    asm volatile("cp.async.wait_group %0;" :: "n"(N) : "memory");
}

// ---------------------------------------------------------------------------
// K1: u[b,i,jm] = sum_n x[b,i,n] * w[i,n,jm]; writes 2-i chunk prefix sums as
// fp16. Grid: (512 i-groups, 2 jm-halves) = 1024 blocks x 256 threads.
// ---------------------------------------------------------------------------
__global__ void __launch_bounds__(256, 2) k_u_prefix(const float* __restrict__ X,
                                                     const float* __restrict__ W)
{
    __shared__ __align__(16) float x_s[K1_IBLK][NI][BB];
    const int t  = threadIdx.x;
    const int i0 = blockIdx.x * K1_IBLK;
    const int qh = blockIdx.y * 256;          // quad offset of this jm-half

#pragma unroll
    for (int rep = 0; rep < 4; rep++) {
        const int idx = t + rep * 256;
        const int ci = idx >> 8, rem = idx & 255, n = rem >> 4, b = rem & 15;
        x_s[ci][n][b] = X[((size_t)b * CI + (i0 + ci)) * NI + n];
    }
    __syncthreads();

    ull acc2[8][4];   // [b-pair][q]: packed (acc[2bp][q], acc[2bp+1][q])

    const float4* W4 = (const float4*)W;
    uint2*        U2 = (uint2*)g_Uh;              // 4 halfs per uint2
    const int     tq = qh + t;                    // this thread's quad index

    float4 cur[4];
#pragma unroll
    for (int k = 0; k < 4; k++)
        cur[k] = W4[(size_t)(i0 * NI + k) * (JM / 4) + tq];

#pragma unroll 4
    for (int g = 0; g < K1_IBLK * 4; g++) {
        const int ci = g >> 2;
        const int i  = i0 + ci;

        float4 nxt[4];
        if (g < K1_IBLK * 4 - 1) {
            const int g1 = g + 1;
            const int base_n = (i0 + (g1 >> 2)) * NI + (g1 & 3) * 4;
#pragma unroll
            for (int k = 0; k < 4; k++)
                nxt[k] = W4[(size_t)(base_n + k) * (JM / 4) + tq];
        }

        if ((g & 7) == 0) {
#pragma unroll
            for (int bp = 0; bp < 8; bp++)
#pragma unroll
                for (int q = 0; q < 4; q++) acc2[bp][q] = 0ull;
        }

#pragma unroll
        for (int k = 0; k < 4; k++) {
            const int n = (g & 3) * 4 + k;
            const ulonglong2* xs16 = (const ulonglong2*)&x_s[ci][n][0];
            const float4 wv = cur[k];
            const ull wd0 = pack2(wv.x, wv.x);
            const ull wd1 = pack2(wv.y, wv.y);
            const ull wd2 = pack2(wv.z, wv.z);
            const ull wd3 = pack2(wv.w, wv.w);
#pragma unroll
            for (int bpp = 0; bpp < 4; bpp++) {
                const ulonglong2 xp2 = xs16[bpp];
                fma2(acc2[2*bpp  ][0], xp2.x, wd0);
                fma2(acc2[2*bpp  ][1], xp2.x, wd1);
                fma2(acc2[2*bpp  ][2], xp2.x, wd2);
                fma2(acc2[2*bpp  ][3], xp2.x, wd3);
                fma2(acc2[2*bpp+1][0], xp2.y, wd0);
                fma2(acc2[2*bpp+1][1], xp2.y, wd1);
                fma2(acc2[2*bpp+1][2], xp2.y, wd2);
                fma2(acc2[2*bpp+1][3], xp2.y, wd3);
            }
        }

        if ((g & 3) == 3) {
#pragma unroll
            for (int bp = 0; bp < 8; bp++) {
                const float2 a0 = unpack2(acc2[bp][0]);
                const float2 a1 = unpack2(acc2[bp][1]);
                const float2 a2 = unpack2(acc2[bp][2]);
                const float2 a3 = unpack2(acc2[bp][3]);
                __half2 lo0 = __floats2half2_rn(a0.x, a1.x);
                __half2 lo1 = __floats2half2_rn(a2.x, a3.x);
                __half2 hi0 = __floats2half2_rn(a0.y, a1.y);
                __half2 hi1 = __floats2half2_rn(a2.y, a3.y);
                uint2 vlo, vhi;
                vlo.x = *(unsigned*)&lo0; vlo.y = *(unsigned*)&lo1;
                vhi.x = *(unsigned*)&hi0; vhi.y = *(unsigned*)&hi1;
                U2[(size_t)(i * BB + 2*bp)     * (JM/4) + tq] = vlo;
                U2[(size_t)(i * BB + 2*bp + 1) * (JM/4) + tq] = vhi;
            }
        }
#pragma unroll
        for (int k = 0; k < 4; k++) cur[k] = nxt[k];
    }
}

// ---------------------------------------------------------------------------
// K2: s0[b,jm] = sum over odd-i prefix rows (chunk=2). g_s zero beforehand.
// ---------------------------------------------------------------------------
__global__ void __launch_bounds__(256) k_s0_reduce()
{
    const int bid = blockIdx.x;
    const int cq  = bid & 3;
    const int jmc = (bid >> 2) & 7;
    const int b   = bid >> 5;
    const int jm  = jmc * 256 + threadIdx.x;
    const int c0  = cq * (CI / 2 / 4);

    float a = 0.0f;
#pragma unroll 8
    for (int c = 0; c < CI / 2 / 4; c++) {
        const int i = (c0 + c) * 2 + 1;
        a += __half2float(g_Uh[(size_t)(i * BB + b) * JM + jm]);
    }
    atomicAdd(&g_s[b * JM + jm], a);
}

// ---- fp16 row -> packed float2 pairs ----------------------------------------
__device__ __forceinline__ void cvt_row_pk(const uint4& p, ull* u2) {
    float2 f;
    f = __half22float2(*(__half2*)&p.x); u2[0] = pack2(f.x, f.y);
    f = __half22float2(*(__half2*)&p.y); u2[1] = pack2(f.x, f.y);
    f = __half22float2(*(__half2*)&p.z); u2[2] = pack2(f.x, f.y);
    f = __half22float2(*(__half2*)&p.w); u2[3] = pack2(f.x, f.y);
}

// ---- Phase A step: wait ladder + dots for chunk C ---------------------------
// Pending groups at window entry are always 8 (own 4 + next window's 4,
// possibly empty), so the ladder waits 7,6,5,4.
template<int C>
__device__ __forceinline__ void phaseA_step(const uint4* slab, float* dsm,
                                            int t, int gl, int j, const ull* v2)
{
    cp_waitN<7 - C>();
    const uint4 A = slab[(2*C + 0) * 256 + t];   // P0 (u_{2C})
    const uint4 B = slab[(2*C + 1) * 256 + t];   // P1 (u_{2C}+u_{2C+1})
    ull p0[4], p1[4];
    cvt_row_pk(A, p0); cvt_row_pk(B, p1);
    ull aA = 0ull, aP = 0ull;
#pragma unroll
    for (int k = 0; k < 4; k++) { fma2(aA, v2[k], p0[k]); fma2(aP, v2[k], p1[k]); }
    float2 fA = unpack2(aA); float dA = fA.x + fA.y;
    float2 fP = unpack2(aP); float dP = fP.x + fP.y;
    dA += __shfl_xor_sync(0xffffffffu, dA, 1);
    dA += __shfl_xor_sync(0xffffffffu, dA, 2);
    dP += __shfl_xor_sync(0xffffffffu, dP, 1);
    dP += __shfl_xor_sync(0xffffffffu, dP, 2);
    if (gl == 0) {
        dsm[(2*C    ) * CJ + j] = dA;         // logit for even i
        dsm[(2*C + 1) * CJ + j] = dP - dA;    // logit for odd i
    }
}

// ---------------------------------------------------------------------------
// Routing pass, 3-phase, DOUBLE-BUFFERED 8-i windows: while window k runs
// A/B/C on slab[k&1], window k+1 is already in flight into slab[(k+1)&1],
// and window k+2 is issued as soon as k's Phase C is done -> loads never
// stop (fixes the per-window burst/drain bubble identified in R13/R14).
// Slab columns are thread-private (each thread only touches its own 16B per
// slot), so only the dsm hazards need barriers (3 per window).
// Uses whatever v is in g_v (pass1: v0; pass2: v0+v1 — logit identity).
// Grid (64, 16) x 256 threads; thread owns jm [8t,8t+8), j = t>>2.
// ---------------------------------------------------------------------------
__global__ void __launch_bounds__(256) k_route()
{
    extern __shared__ __align__(16) char smem[];
    float* dsm = (float*)(smem + 2 * RT_BUFB);           // [8][64] 2KB

    const int t  = threadIdx.x;
    const int l  = t & 31;
    const int wp = t >> 5;
    const int gl = t & 3;
    const int b  = blockIdx.y;
    const int j  = t >> 2;

    ull v2[4];   // v packed as float2 pairs
    {
        const float4* gv4 = (const float4*)g_v;
        float4 va = gv4[b * (JM/4) + 2*t];
        float4 vb = gv4[b * (JM/4) + 2*t + 1];
        v2[0] = pack2(va.x, va.y); v2[1] = pack2(va.z, va.w);
        v2[2] = pack2(vb.x, vb.y); v2[3] = pack2(vb.z, vb.w);
    }

    ull s2[4];   // s accumulator, packed pairs (across all windows)
#pragma unroll
    for (int k = 0; k < 4; k++) s2[k] = 0ull;

    const size_t rbytes = (size_t)BB * JM * 2;           // bytes per i-row
    const uint smem_t = (uint)__cvta_generic_to_shared(smem) + 16 * t;

    // issue window w's 4 chunk-groups into slab buffer (w&1)
    auto issue = [&](int w) {
        const int i0 = blockIdx.x * RT_ICHUNK + w * (CI / RT_WND);
        const char* gp = (const char*)g_Uh
                       + ((size_t)i0 * BB + b) * (JM * 2) + 16 * t;
        const uint sb = smem_t + (uint)(w & 1) * RT_BUFB;
#pragma unroll
        for (int c = 0; c < RT_CH; c++) {
            cp16(sb + (2*c + 0) * 4096, gp + (size_t)(2*c)     * rbytes);
            cp16(sb + (2*c + 1) * 4096, gp + (size_t)(2*c + 1) * rbytes);
            cp_commit();
        }
    };

    issue(0);
    issue(1);

#pragma unroll 1
    for (int wnd = 0; wnd < RT_WND; wnd++) {
        const uint4* sl = (const uint4*)(smem + (wnd & 1) * RT_BUFB);

        // ---- Phase A: dots (wait ladder, no barriers) ----
        phaseA_step<0>(sl, dsm, t, gl, j, v2);
        phaseA_step<1>(sl, dsm, t, gl, j, v2);
        phaseA_step<2>(sl, dsm, t, gl, j, v2);
        phaseA_step<3>(sl, dsm, t, gl, j, v2);
        __syncthreads();

        // ---- Phase B: warp-local softmax (warp wp owns i = wp) ----
        {
            const float zl = dsm[wp * CJ + l];
            const float zh = dsm[wp * CJ + l + 32];
            const float el = exp2f(zl * AL2E);
            const float eh = exp2f(zh * AL2E);
            float es = el + eh;
#pragma unroll
            for (int o = 16; o > 0; o >>= 1)
                es += __shfl_xor_sync(0xffffffffu, es, o);
            const float inv = __fdividef(64.0f, es);
            dsm[wp * CJ + l]      = el * inv;
            dsm[wp * CJ + l + 32] = eh * inv;
        }
        __syncthreads();

        // ---- Phase C: accumulate from SMEM slab ----
#pragma unroll
        for (int c = 0; c < RT_CH; c++) {
            const uint4 A = sl[(2*c + 0) * 256 + t];
            const uint4 B = sl[(2*c + 1) * 256 + t];
            ull p0[4], p1[4];
            cvt_row_pk(A, p0); cvt_row_pk(B, p1);
            const float ccA = dsm[(2*c    ) * CJ + j];
            const float ccB = dsm[(2*c + 1) * CJ + j];
            const ull gg = pack2(ccA - ccB, ccA - ccB);
            const ull cb = pack2(ccB, ccB);
#pragma unroll
            for (int k = 0; k < 4; k++) { fma2(s2[k], p0[k], gg); fma2(s2[k], p1[k], cb); }
        }
        __syncthreads();   // dsm reuse (A of wnd+1) + slab reuse (issue below)

        // refill this buffer with window wnd+2 (empty commits keep the
        // group count uniform so the wait ladder constants stay valid)
        if (wnd + 2 < RT_WND) {
            issue(wnd + 2);
        } else {
            cp_commit(); cp_commit(); cp_commit(); cp_commit();
        }
    }

#pragma unroll
    for (int k = 0; k < 4; k++) {
        const float2 f = unpack2(s2[k]);
        atomicAdd(&g_s[b * JM + 8*t + 2*k],     f.x);
        atomicAdd(&g_s[b * JM + 8*t + 2*k + 1], f.y);
    }
}

// ---------------------------------------------------------------------------
// Squash. mode: dst!=null -> write dst; else accum? g_v += vnew : g_v = vnew.
// Always re-zeroes g_s.
// ---------------------------------------------------------------------------
__global__ void __launch_bounds__(512) k_squash(float* dst, int accum)
{
    const int t    = threadIdx.x;
    const int gw   = blockIdx.x * 16 + (t >> 5);
    const int lane = t & 31;
    const int b    = gw >> 6;
    const int j    = gw & 63;
    const int idx  = b * JM + j * NJ + lane;

    const float s = g_s[idx];
    float sq = s * s;
#pragma unroll
    for (int o = 16; o > 0; o >>= 1)
        sq += __shfl_xor_sync(0xffffffffu, sq, o);

    const float coef = (sq / (1.0f + sq)) * rsqrtf(sq + 1e-7f);
    const float vnew = s * coef;
    if (dst)        dst[idx] = vnew;
    else if (accum) g_v[idx] += vnew;     // g_v: v0 -> v0+v1
    else            g_v[idx] = vnew;      // g_v = v0
    g_s[idx] = 0.0f;
}

// ---------------------------------------------------------------------------
extern "C" void kernel_launch(void* const* d_in, const int* in_sizes, int n_in,
                              void* d_out, int out_size)
{
    const float* X = (const float*)d_in[0];
    const float* W = (const float*)d_in[1];
    if (n_in >= 2 && in_sizes[0] > in_sizes[1]) {   // defensive order check
        const float* tmp = X; X = W; W = tmp;
    }
    float* out = (float*)d_out;

    static int smem_set = 0;
    if (!smem_set) {
        cudaFuncSetAttribute(k_route,
                             cudaFuncAttributeMaxDynamicSharedMemorySize,
                             RT_SMEM);
        smem_set = 1;
    }

    const dim3 rt_grid(CI / (RT_ICHUNK * RT_WND), BB);   // (64, 16)

    k_u_prefix<<<dim3(CI / K1_IBLK, 2), 256>>>(X, W);
    k_s0_reduce<<<512, 256>>>();
    k_squash<<<64, 512>>>(nullptr, 0);                   // g_v = v0, zero g_s
    k_route<<<rt_grid, 256, RT_SMEM>>>();                // b1 = <v0,u>, s1
    k_squash<<<64, 512>>>(nullptr, 1);                   // g_v = v0+v1, zero g_s
    k_route<<<rt_grid, 256, RT_SMEM>>>();                // b2 = <v0+v1,u>, s2
    k_squash<<<64, 512>>>(out, 0);                       // out = v2, zero g_s
    (void)out_size;
}

// round 17
// speedup vs baseline: 1.1499x; 1.1499x over previous
#include <cuda_runtime.h>
#include <cuda_fp16.h>
#include <cstdint>
#include <math.h>

// Problem constants
#define BB   16      // batch
#define CI   2048    // input capsules
#define NI   16      // input capsule dim
#define CJ   64      // output capsules
#define NJ   32      // output capsule dim
#define JM   2048    // CJ*NJ
#define K1_CHUNK 2   // i's per prefix chunk (acc reset period)
#define K1_IBLK  4   // i's per K1 block
#define RT_ICHUNK 16                      // i's per window
#define RT_WND    2                       // windows per block (i0, i0+CI/2)
#define RT_CH     (RT_ICHUNK / 2)         // 8 chunks per window
#define RT_SMEM   (RT_CH * 2 * 4096 + RT_ICHUNK * CJ * 4)   // 64KB slab + 4KB dsm
#define AL2E 11.541560327111707f          // 8 * log2(e)

typedef unsigned long long ull;
typedef unsigned int       uint;

// g_Uh: chunk-local PREFIX sums of u over i (chunk=2), fp16, layout [i][b][jm]
static __device__ __half g_Uh[(size_t)CI * BB * JM];  // 134 MB
static __device__ float  g_s[BB * JM];                // s accumulator (BSS zero)
static __device__ float  g_v[BB * JM];                // v0, then v0+v1

// ---- packed fp32 pair helpers (fma.rn.f32x2, sm_100+) ----------------------
__device__ __forceinline__ void fma2(ull& d, ull a, ull b) {
    asm("fma.rn.f32x2 %0, %1, %2, %0;" : "+l"(d) : "l"(a), "l"(b));
}
__device__ __forceinline__ ull pack2(float x, float y) {
    ull r; asm("mov.b64 %0, {%1, %2};" : "=l"(r) : "f"(x), "f"(y)); return r;
}
__device__ __forceinline__ float2 unpack2(ull v) {
    float2 r; asm("mov.b64 {%0, %1}, %2;" : "=f"(r.x), "=f"(r.y) : "l"(v)); return r;
}

// ---- cp.async helpers -------------------------------------------------------
__device__ __forceinline__ void cp16(uint s, const void* g) {
    asm volatile("cp.async.cg.shared.global [%0], [%1], 16;"
                 :: "r"(s), "l"(g) : "memory");
}
__device__ __forceinline__ void cp_commit() {
    asm volatile("cp.async.commit_group;" ::: "memory");
}
template<int N> __device__ __forceinline__ void cp_waitN() {
    asm volatile("cp.async.wait_group %0;" :: "n"(N) : "memory");
}

// ---------------------------------------------------------------------------
// K1: u[b,i,jm] = sum_n x[b,i,n] * w[i,n,jm]; writes 2-i chunk prefix sums as
// fp16. Grid: (512 i-groups, 2 jm-halves) = 1024 blocks x 256 threads.
// ---------------------------------------------------------------------------
__global__ void __launch_bounds__(256, 2) k_u_prefix(const float* __restrict__ X,
                                                     const float* __restrict__ W)
{
    __shared__ __align__(16) float x_s[K1_IBLK][NI][BB];
    const int t  = threadIdx.x;
    const int i0 = blockIdx.x * K1_IBLK;
    const int qh = blockIdx.y * 256;          // quad offset of this jm-half

#pragma unroll
    for (int rep = 0; rep < 4; rep++) {
        const int idx = t + rep * 256;
        const int ci = idx >> 8, rem = idx & 255, n = rem >> 4, b = rem & 15;
        x_s[ci][n][b] = X[((size_t)b * CI + (i0 + ci)) * NI + n];
    }
    __syncthreads();

    ull acc2[8][4];   // [b-pair][q]: packed (acc[2bp][q], acc[2bp+1][q])

    const float4* W4 = (const float4*)W;
    uint2*        U2 = (uint2*)g_Uh;              // 4 halfs per uint2
    const int     tq = qh + t;                    // this thread's quad index

    float4 cur[4];
#pragma unroll
    for (int k = 0; k < 4; k++)
        cur[k] = W4[(size_t)(i0 * NI + k) * (JM / 4) + tq];

#pragma unroll 4
    for (int g = 0; g < K1_IBLK * 4; g++) {
        const int ci = g >> 2;
        const int i  = i0 + ci;

        float4 nxt[4];
        if (g < K1_IBLK * 4 - 1) {
            const int g1 = g + 1;
            const int base_n = (i0 + (g1 >> 2)) * NI + (g1 & 3) * 4;
#pragma unroll
            for (int k = 0; k < 4; k++)
                nxt[k] = W4[(size_t)(base_n + k) * (JM / 4) + tq];
        }

        if ((g & 7) == 0) {
#pragma unroll
            for (int bp = 0; bp < 8; bp++)
#pragma unroll
                for (int q = 0; q < 4; q++) acc2[bp][q] = 0ull;
        }

#pragma unroll
        for (int k = 0; k < 4; k++) {
            const int n = (g & 3) * 4 + k;
            const ulonglong2* xs16 = (const ulonglong2*)&x_s[ci][n][0];
            const float4 wv = cur[k];
            const ull wd0 = pack2(wv.x, wv.x);
            const ull wd1 = pack2(wv.y, wv.y);
            const ull wd2 = pack2(wv.z, wv.z);
            const ull wd3 = pack2(wv.w, wv.w);
#pragma unroll
            for (int bpp = 0; bpp < 4; bpp++) {
                const ulonglong2 xp2 = xs16[bpp];
                fma2(acc2[2*bpp  ][0], xp2.x, wd0);
                fma2(acc2[2*bpp  ][1], xp2.x, wd1);
                fma2(acc2[2*bpp  ][2], xp2.x, wd2);
                fma2(acc2[2*bpp  ][3], xp2.x, wd3);
                fma2(acc2[2*bpp+1][0], xp2.y, wd0);
                fma2(acc2[2*bpp+1][1], xp2.y, wd1);
                fma2(acc2[2*bpp+1][2], xp2.y, wd2);
                fma2(acc2[2*bpp+1][3], xp2.y, wd3);
            }
        }

        if ((g & 3) == 3) {
#pragma unroll
            for (int bp = 0; bp < 8; bp++) {
                const float2 a0 = unpack2(acc2[bp][0]);
                const float2 a1 = unpack2(acc2[bp][1]);
                const float2 a2 = unpack2(acc2[bp][2]);
                const float2 a3 = unpack2(acc2[bp][3]);
                __half2 lo0 = __floats2half2_rn(a0.x, a1.x);
                __half2 lo1 = __floats2half2_rn(a2.x, a3.x);
                __half2 hi0 = __floats2half2_rn(a0.y, a1.y);
                __half2 hi1 = __floats2half2_rn(a2.y, a3.y);
                uint2 vlo, vhi;
                vlo.x = *(unsigned*)&lo0; vlo.y = *(unsigned*)&lo1;
                vhi.x = *(unsigned*)&hi0; vhi.y = *(unsigned*)&hi1;
                U2[(size_t)(i * BB + 2*bp)     * (JM/4) + tq] = vlo;
                U2[(size_t)(i * BB + 2*bp + 1) * (JM/4) + tq] = vhi;
            }
        }
#pragma unroll
        for (int k = 0; k < 4; k++) cur[k] = nxt[k];
    }
}

// ---------------------------------------------------------------------------
// K2: s0[b,jm] = sum over odd-i prefix rows (chunk=2). g_s zero beforehand.
// ---------------------------------------------------------------------------
__global__ void __launch_bounds__(256) k_s0_reduce()
{
    const int bid = blockIdx.x;
    const int cq  = bid & 3;
    const int jmc = (bid >> 2) & 7;
    const int b   = bid >> 5;
    const int jm  = jmc * 256 + threadIdx.x;
    const int c0  = cq * (CI / 2 / 4);

    float a = 0.0f;
#pragma unroll 8
    for (int c = 0; c < CI / 2 / 4; c++) {
        const int i = (c0 + c) * 2 + 1;
        a += __half2float(g_Uh[(size_t)(i * BB + b) * JM + jm]);
    }
    atomicAdd(&g_s[b * JM + jm], a);
}

// ---- fp16 row -> packed float2 pairs ----------------------------------------
__device__ __forceinline__ void cvt_row_pk(const uint4& p, ull* u2) {
    float2 f;
    f = __half22float2(*(__half2*)&p.x); u2[0] = pack2(f.x, f.y);
    f = __half22float2(*(__half2*)&p.y); u2[1] = pack2(f.x, f.y);
    f = __half22float2(*(__half2*)&p.z); u2[2] = pack2(f.x, f.y);
    f = __half22float2(*(__half2*)&p.w); u2[3] = pack2(f.x, f.y);
}

// ---- Phase A step: wait ladder + dots for chunk C ---------------------------
template<int C>
__device__ __forceinline__ void phaseA_step(const uint4* slab, float* dsm,
                                            int t, int gl, int j, const ull* v2)
{
    cp_waitN<RT_CH - 1 - C>();
    const uint4 A = slab[(2*C + 0) * 256 + t];   // P0 (u_{2C})
    const uint4 B = slab[(2*C + 1) * 256 + t];   // P1 (u_{2C}+u_{2C+1})
    ull p0[4], p1[4];
    cvt_row_pk(A, p0); cvt_row_pk(B, p1);
    ull aA = 0ull, aP = 0ull;
#pragma unroll
    for (int k = 0; k < 4; k++) { fma2(aA, v2[k], p0[k]); fma2(aP, v2[k], p1[k]); }
    float2 fA = unpack2(aA); float dA = fA.x + fA.y;
    float2 fP = unpack2(aP); float dP = fP.x + fP.y;
    dA += __shfl_xor_sync(0xffffffffu, dA, 1);
    dA += __shfl_xor_sync(0xffffffffu, dA, 2);
    dP += __shfl_xor_sync(0xffffffffu, dP, 1);
    dP += __shfl_xor_sync(0xffffffffu, dP, 2);
    if (gl == 0) {
        dsm[(2*C    ) * CJ + j] = dA;         // logit for even i
        dsm[(2*C + 1) * CJ + j] = dP - dA;    // logit for odd i
    }
}

// ---------------------------------------------------------------------------
// Routing pass, 3-phase with SMEM-resident slice (R13 optimum — do not touch).
// Uses whatever v is in g_v (pass1: v0; pass2: v0+v1 — logit identity).
// Grid (64, 16) x 256 threads; thread owns jm [8t,8t+8), j = t>>2.
// ---------------------------------------------------------------------------
__global__ void __launch_bounds__(256) k_route()
{
    extern __shared__ __align__(16) char smem[];
    uint4* slab = (uint4*)smem;                          // [16 slots][256] 64KB
    float* dsm  = (float*)(smem + RT_CH * 2 * 4096);     // [16][64] 4KB

    const int t  = threadIdx.x;
    const int l  = t & 31;
    const int wp = t >> 5;
    const int gl = t & 3;
    const int b  = blockIdx.y;
    const int j  = t >> 2;

    ull v2[4];   // v packed as float2 pairs
    {
        const float4* gv4 = (const float4*)g_v;
        float4 va = gv4[b * (JM/4) + 2*t];
        float4 vb = gv4[b * (JM/4) + 2*t + 1];
        v2[0] = pack2(va.x, va.y); v2[1] = pack2(va.z, va.w);
        v2[2] = pack2(vb.x, vb.y); v2[3] = pack2(vb.z, vb.w);
    }

    ull s2[4];   // s accumulator, packed pairs (across both windows)
#pragma unroll
    for (int k = 0; k < 4; k++) s2[k] = 0ull;

    const size_t rbytes = (size_t)BB * JM * 2;           // bytes per i-row
    const uint slab_t = (uint)__cvta_generic_to_shared(smem) + 16 * t;

#pragma unroll 1
    for (int wnd = 0; wnd < RT_WND; wnd++) {
        const int i0 = blockIdx.x * RT_ICHUNK + wnd * (CI / 2);
        const char* gp = (const char*)g_Uh
                       + ((size_t)i0 * BB + b) * (JM * 2) + 16 * t;

        // issue all chunks (64KB in flight per block)
#pragma unroll
        for (int c = 0; c < RT_CH; c++) {
            cp16(slab_t + (2*c + 0) * 4096, gp + (size_t)(2*c)     * rbytes);
            cp16(slab_t + (2*c + 1) * 4096, gp + (size_t)(2*c + 1) * rbytes);
            cp_commit();
        }

        // ---- Phase A: dots (no barriers) ----
        phaseA_step<0>(slab, dsm, t, gl, j, v2);
        phaseA_step<1>(slab, dsm, t, gl, j, v2);
        phaseA_step<2>(slab, dsm, t, gl, j, v2);
        phaseA_step<3>(slab, dsm, t, gl, j, v2);
        phaseA_step<4>(slab, dsm, t, gl, j, v2);
        phaseA_step<5>(slab, dsm, t, gl, j, v2);
        phaseA_step<6>(slab, dsm, t, gl, j, v2);
        phaseA_step<7>(slab, dsm, t, gl, j, v2);
        __syncthreads();

        // ---- Phase B: warp-local softmax (warp owns i = 2wp, 2wp+1) ----
#pragma unroll
        for (int r = 0; r < 2; r++) {
            const int i = 2 * wp + r;
            const float zl = dsm[i * CJ + l];
            const float zh = dsm[i * CJ + l + 32];
            const float el = exp2f(zl * AL2E);
            const float eh = exp2f(zh * AL2E);
            float es = el + eh;
#pragma unroll
            for (int o = 16; o > 0; o >>= 1)
                es += __shfl_xor_sync(0xffffffffu, es, o);
            const float inv = __fdividef(64.0f, es);
            dsm[i * CJ + l]      = el * inv;
            dsm[i * CJ + l + 32] = eh * inv;
        }
        __syncthreads();

        // ---- Phase C: accumulate from SMEM slab ----
#pragma unroll
        for (int c = 0; c < RT_CH; c++) {
            const uint4 A = slab[(2*c + 0) * 256 + t];
            const uint4 B = slab[(2*c + 1) * 256 + t];
            ull p0[4], p1[4];
            cvt_row_pk(A, p0); cvt_row_pk(B, p1);
            const float ccA = dsm[(2*c    ) * CJ + j];
            const float ccB = dsm[(2*c + 1) * CJ + j];
            const ull gg = pack2(ccA - ccB, ccA - ccB);
            const ull cb = pack2(ccB, ccB);
#pragma unroll
            for (int k = 0; k < 4; k++) { fma2(s2[k], p0[k], gg); fma2(s2[k], p1[k], cb); }
        }
        if (wnd + 1 < RT_WND) __syncthreads();  // slab reuse protection
    }

#pragma unroll
    for (int k = 0; k < 4; k++) {
        const float2 f = unpack2(s2[k]);
        atomicAdd(&g_s[b * JM + 8*t + 2*k],     f.x);
        atomicAdd(&g_s[b * JM + 8*t + 2*k + 1], f.y);
    }
}

// ---------------------------------------------------------------------------
// Squash. mode: dst!=null -> write dst; else accum? g_v += vnew : g_v = vnew.
// Always re-zeroes g_s. Regridded: 256 blocks x 128 threads (4 warps/block,
// warp per (b,j)) so all 148 SMs participate (was 64 blocks @ 26% occ).
// ---------------------------------------------------------------------------
__global__ void __launch_bounds__(128) k_squash(float* dst, int accum)
{
    const int t    = threadIdx.x;
    const int gw   = blockIdx.x * 4 + (t >> 5);   // global warp = (b,j) pair
    const int lane = t & 31;
    const int b    = gw >> 6;
    const int j    = gw & 63;
    const int idx  = b * JM + j * NJ + lane;

    const float s = g_s[idx];
    float sq = s * s;
#pragma unroll
    for (int o = 16; o > 0; o >>= 1)
        sq += __shfl_xor_sync(0xffffffffu, sq, o);

    const float coef = (sq / (1.0f + sq)) * rsqrtf(sq + 1e-7f);
    const float vnew = s * coef;
    if (dst)        dst[idx] = vnew;
    else if (accum) g_v[idx] += vnew;     // g_v: v0 -> v0+v1
    else            g_v[idx] = vnew;      // g_v = v0
    g_s[idx] = 0.0f;
}

// ---------------------------------------------------------------------------
extern "C" void kernel_launch(void* const* d_in, const int* in_sizes, int n_in,
                              void* d_out, int out_size)
{
    const float* X = (const float*)d_in[0];
    const float* W = (const float*)d_in[1];
    if (n_in >= 2 && in_sizes[0] > in_sizes[1]) {   // defensive order check
        const float* tmp = X; X = W; W = tmp;
    }
    float* out = (float*)d_out;

    static int smem_set = 0;
    if (!smem_set) {
        cudaFuncSetAttribute(k_route,
                             cudaFuncAttributeMaxDynamicSharedMemorySize,
                             RT_SMEM);
        smem_set = 1;
    }

    const dim3 rt_grid(CI / (RT_ICHUNK * RT_WND), BB);   // (64, 16)

    k_u_prefix<<<dim3(CI / K1_IBLK, 2), 256>>>(X, W);
    k_s0_reduce<<<512, 256>>>();
    k_squash<<<256, 128>>>(nullptr, 0);                  // g_v = v0, zero g_s
    k_route<<<rt_grid, 256, RT_SMEM>>>();                // b1 = <v0,u>, s1
    k_squash<<<256, 128>>>(nullptr, 1);                  // g_v = v0+v1, zero g_s
    k_route<<<rt_grid, 256, RT_SMEM>>>();                // b2 = <v0+v1,u>, s2
    k_squash<<<256, 128>>>(out, 0);                      // out = v2, zero g_s
    (void)out_size;
}